// round 8
// baseline (speedup 1.0000x reference)
#include <cuda_runtime.h>
#include <math.h>

// ---------------- problem constants ----------------
#define SLOTS      85      // 81 classes + 4 box coords
#define NBINS      4096
#define HIST_LO   (-8.0f)
#define HIST_INVW (256.0f)   // NBINS / 16
#define NBLOCKS    592       // 4 per SM (register-limited occupancy), ONE wave

// ---------------- device scratch (statically zero-initialized; finalize
// kernel re-zeroes it at the end of every replay) ----------------
__device__ int    g_npos;
__device__ double g_pos_loss;
__device__ double g_loc_loss;
__device__ int    g_hist_cnt[NBINS];
__device__ float  g_hist_sum[NBINS];

// ---------------- K1: one-hot gather pass, warp = 4 anchors ----------------
// y_true class rows are one-hot: conf = -y_pred[hot]. Background value
// y_pred[r+0] is loaded UP FRONT (independent of the reduction) since 98% of
// anchors are negatives (hot==0); only positives pay a dependent gather.
__global__ __launch_bounds__(256) void ssd_main_kernel(
    const float* __restrict__ yp,
    const float* __restrict__ yt,
    int nanch)
{
    __shared__ int   s_cnt[NBINS];
    __shared__ float s_sum[NBINS];
    for (int i = threadIdx.x; i < NBINS; i += 256) { s_cnt[i] = 0; s_sum[i] = 0.0f; }
    __syncthreads();

    const int lane = threadIdx.x & 31;
    const int warp = threadIdx.x >> 5;

    const long long wid    = (long long)blockIdx.x * 8 + warp;
    const long long stride = (long long)NBLOCKS * 8 * 4;   // anchors per grid step

    float accPos = 0.0f, accLoc = 0.0f;
    int   accN = 0;

    for (long long a0 = wid * 4; a0 < nanch; a0 += stride) {
        // validity + row bases
        bool   v0 = true,                v1 = (a0 + 1 < nanch);
        bool   v2 = (a0 + 2 < nanch),    v3 = (a0 + 3 < nanch);
        size_t r0 = (size_t)(a0    ) * SLOTS;
        size_t r1 = (size_t)(a0 + 1) * SLOTS;
        size_t r2 = (size_t)(a0 + 2) * SLOTS;
        size_t r3 = (size_t)(a0 + 3) * SLOTS;

        // ---- front-batched independent loads (12 yt + 1 yp-bg) ----
        float t0a = yt[r0 + lane];
        float t0b = yt[r0 + lane + 32];
        float t0c = (lane < 17) ? yt[r0 + lane + 64] : 0.0f;
        float t1a = v1 ? yt[r1 + lane]       : 0.0f;
        float t1b = v1 ? yt[r1 + lane + 32]  : 0.0f;
        float t1c = (v1 && lane < 17) ? yt[r1 + lane + 64] : 0.0f;
        float t2a = v2 ? yt[r2 + lane]       : 0.0f;
        float t2b = v2 ? yt[r2 + lane + 32]  : 0.0f;
        float t2c = (v2 && lane < 17) ? yt[r2 + lane + 64] : 0.0f;
        float t3a = v3 ? yt[r3 + lane]       : 0.0f;
        float t3b = v3 ? yt[r3 + lane + 32]  : 0.0f;
        float t3c = (v3 && lane < 17) ? yt[r3 + lane + 64] : 0.0f;

        // background logits: lane i<4 loads yp[(a0+i)*SLOTS]
        float bg = 0.0f;
        if (lane < 4 && a0 + lane < nanch)
            bg = yp[(size_t)(a0 + lane) * SLOTS];

        // ---- hot class index per anchor (exactly one class slot nonzero) ----
        int la0 = -1, la1 = -1, la2 = -1, la3 = -1;
        if (t0a != 0.0f) la0 = lane;
        if (t0b != 0.0f) la0 = lane + 32;
        if (t0c != 0.0f) la0 = lane + 64;
        if (t1a != 0.0f) la1 = lane;
        if (t1b != 0.0f) la1 = lane + 32;
        if (t1c != 0.0f) la1 = lane + 64;
        if (t2a != 0.0f) la2 = lane;
        if (t2b != 0.0f) la2 = lane + 32;
        if (t2c != 0.0f) la2 = lane + 64;
        if (t3a != 0.0f) la3 = lane;
        if (t3b != 0.0f) la3 = lane + 32;
        if (t3c != 0.0f) la3 = lane + 64;

        int hot0 = __reduce_max_sync(0xffffffffu, la0);
        int hot1 = __reduce_max_sync(0xffffffffu, la1);
        int hot2 = __reduce_max_sync(0xffffffffu, la2);
        int hot3 = __reduce_max_sync(0xffffffffu, la3);

        // ---- per-anchor bookkeeping: lane i (0..3) owns anchor i ----
        if (lane < 4) {
            int    h  = hot0;
            size_t r  = r0;
            bool   v  = v0;
            if (lane == 1) { h = hot1; r = r1; v = v1; }
            if (lane == 2) { h = hot2; r = r2; v = v2; }
            if (lane == 3) { h = hot3; r = r3; v = v3; }

            if (v) {
                if (h > 0) {                         // positive (~2%): gather
                    float conf = -yp[r + h];
                    accN++; accPos += conf;
                } else {                              // negative: bg preloaded
                    float conf = -bg;
                    int bin = (int)((conf - HIST_LO) * HIST_INVW);
                    bin = max(0, min(NBINS - 1, bin));
                    atomicAdd(&s_cnt[bin], 1);
                    atomicAdd(&s_sum[bin], conf);
                }
            }
        }

        // ---- box smooth-L1: lanes 16..31, anchor j = (lane-16)>>2, coord = lane&3
        if (lane >= 16) {
            int j = (lane - 16) >> 2;
            int coord = lane & 3;
            int    h = hot0;  size_t r = r0;  bool v = v0;
            if (j == 1) { h = hot1; r = r1; v = v1; }
            if (j == 2) { h = hot2; r = r2; v = v2; }
            if (j == 3) { h = hot3; r = r3; v = v3; }
            if (v && h > 0) {                        // positives only (~2%)
                size_t rb = r + 81 + coord;
                float d  = yp[rb] - yt[rb];
                float ad = fabsf(d);
                accLoc += (ad < 1.0f) ? 0.5f * d * d : (ad - 0.5f);
            }
        }
    }

    // ---- warp flush: reduce scattered accumulators, one atomic set per warp
    #pragma unroll
    for (int off = 16; off; off >>= 1) {
        accPos += __shfl_down_sync(0xffffffffu, accPos, off);
        accLoc += __shfl_down_sync(0xffffffffu, accLoc, off);
    }
    int warpN = __reduce_add_sync(0xffffffffu, accN);

    if (lane == 0) {
        if (warpN) {
            atomicAdd(&g_npos, warpN);
            atomicAdd(&g_pos_loss, (double)accPos);
        }
        if (accLoc != 0.0f) atomicAdd(&g_loc_loss, (double)accLoc);
    }

    __syncthreads();
    for (int i = threadIdx.x; i < NBINS; i += 256) {
        int cc = s_cnt[i];
        if (cc) {
            atomicAdd(&g_hist_cnt[i], cc);
            atomicAdd(&g_hist_sum[i], s_sum[i]);
        }
    }
}

// ---------------- K2: single-block finalize (warp-shuffle scan) ------------
__global__ __launch_bounds__(1024) void ssd_finalize_kernel(float* __restrict__ out)
{
    __shared__ int    s_wsum[32];
    __shared__ int    s_woff[32];
    __shared__ double s_neg;

    const int tid  = threadIdx.x;
    const int lane = tid & 31;
    const int wrp  = tid >> 5;

    // thread owns 4 consecutive ranks from the top: rank i -> bin NBINS-1-i
    int  c[4];
    float sf[4];
    #pragma unroll
    for (int k = 0; k < 4; k++) {
        int i = tid * 4 + k;
        int b = NBINS - 1 - i;
        c[k]  = g_hist_cnt[b];
        sf[k] = g_hist_sum[b];
    }
    int total = c[0] + c[1] + c[2] + c[3];

    // warp-local inclusive scan of per-thread totals
    int scan = total;
    #pragma unroll
    for (int off = 1; off < 32; off <<= 1) {
        int v = __shfl_up_sync(0xffffffffu, scan, off);
        if (lane >= off) scan += v;
    }
    if (lane == 31) s_wsum[wrp] = scan;
    if (tid == 0)   s_neg = 0.0;
    __syncthreads();

    // warp 0 scans the 32 warp totals -> exclusive warp offsets
    if (wrp == 0) {
        int w = s_wsum[lane];
        int ws = w;
        #pragma unroll
        for (int off = 1; off < 32; off <<= 1) {
            int v = __shfl_up_sync(0xffffffffu, ws, off);
            if (lane >= off) ws += v;
        }
        s_woff[lane] = ws - w;     // exclusive prefix
    }
    __syncthreads();

    int cumBefore = s_woff[wrp] + (scan - total);  // negatives strictly above

    int npos = g_npos;
    int nneg = (int)(3.0f * (float)npos);

    double contrib = 0.0;
    int cb = cumBefore;
    #pragma unroll
    for (int k = 0; k < 4; k++) {
        int cc = c[k];
        if (cc) {
            if (cb + cc <= nneg) {
                contrib += (double)sf[k];                                    // fully taken
            } else if (cb < nneg) {
                contrib += (double)sf[k] * (double)(nneg - cb) / (double)cc; // straddling
            }
        }
        cb += cc;
    }

    // warp-reduce contrib, one shared atomic per warp
    #pragma unroll
    for (int off = 16; off; off >>= 1)
        contrib += __shfl_down_sync(0xffffffffu, contrib, off);
    if (lane == 0 && contrib != 0.0) atomicAdd(&s_neg, contrib);
    __syncthreads();

    if (tid == 0) {
        double np = (npos > 0) ? (double)npos : 1.0;
        out[0] = (float)((g_pos_loss + s_neg + g_loc_loss) / np);
    }

    // ---- re-zero scratch so the next graph replay starts clean ----
    __syncthreads();
    for (int i = tid; i < NBINS; i += 1024) {
        g_hist_cnt[i] = 0;
        g_hist_sum[i] = 0.0f;
    }
    if (tid == 0) { g_npos = 0; g_pos_loss = 0.0; g_loc_loss = 0.0; }
}

// ---------------- entry point ----------------
extern "C" void kernel_launch(void* const* d_in, const int* in_sizes, int n_in,
                              void* d_out, int out_size)
{
    const float* y_pred = (const float*)d_in[0];
    const float* y_true = (const float*)d_in[1];
    float* out = (float*)d_out;

    int nanch = in_sizes[0] / SLOTS;

    ssd_main_kernel<<<NBLOCKS, 256>>>(y_pred, y_true, nanch);
    ssd_finalize_kernel<<<1, 1024>>>(out);
}

// round 9
// speedup vs baseline: 1.7088x; 1.7088x over previous
#include <cuda_runtime.h>
#include <math.h>

// ---------------- problem constants ----------------
#define SLOTS      85      // 81 classes + 4 box coords
#define NBINS      4096
#define HIST_LO   (-8.0f)
#define HIST_INVW (256.0f)   // NBINS / 16
#define NBLOCKS    592       // 4 blocks/SM (pinned) * 148 SMs = ONE wave

// ---------------- device scratch (statically zero-initialized; finalize
// kernel re-zeroes it at the end of every replay) ----------------
__device__ int    g_npos;
__device__ double g_pos_loss;
__device__ double g_loc_loss;
__device__ int    g_hist_cnt[NBINS];
__device__ float  g_hist_sum[NBINS];

// ---------------- K1: one-hot gather pass, warp = 8 anchors ----------------
// y_true class rows are one-hot: conf = -y_pred[hot]. 25 independent LDGs are
// front-batched per iteration (8 anchors x ~3 yt rows + 8 bg logits via one
// predicated LDG). All row offsets are compile-time immediates off one base.
__global__ __launch_bounds__(256, 4) void ssd_main_kernel(
    const float* __restrict__ yp,
    const float* __restrict__ yt,
    int nanch)
{
    __shared__ int   s_cnt[NBINS];
    __shared__ float s_sum[NBINS];
    for (int i = threadIdx.x; i < NBINS; i += 256) { s_cnt[i] = 0; s_sum[i] = 0.0f; }
    __syncthreads();

    const int lane = threadIdx.x & 31;
    const int warp = threadIdx.x >> 5;

    const int wid    = blockIdx.x * 8 + warp;
    const int stride = NBLOCKS * 8 * 8;          // anchors per grid step

    float accPos = 0.0f, accLoc = 0.0f;
    int   accN = 0;

    for (int a0 = wid * 8; a0 < nanch; a0 += stride) {
        const unsigned base = (unsigned)a0 * SLOTS;   // fits: nanch*85 < 2^31

        if (a0 + 8 <= nanch) {
            // ---- 24 front-batched yt loads (immediates off one base) ----
            float ta[8], tb[8], tc[8];
            #pragma unroll
            for (int j = 0; j < 8; j++) {
                ta[j] = yt[base + j * SLOTS + lane];
                tb[j] = yt[base + j * SLOTS + lane + 32];
                tc[j] = (lane < 17) ? yt[base + j * SLOTS + lane + 64] : 0.0f;
            }
            // background logits: lane j<8 loads yp[(a0+j)*SLOTS]
            float bg = (lane < 8) ? yp[base + lane * SLOTS] : 0.0f;

            // ---- hot class index per anchor (one class slot nonzero) ----
            int hot[8];
            #pragma unroll
            for (int j = 0; j < 8; j++) {
                int la = -1;
                if (ta[j] != 0.0f) la = lane;
                if (tb[j] != 0.0f) la = lane + 32;
                if (tc[j] != 0.0f) la = lane + 64;   // tc==0 for lane>=17
                hot[j] = max(__reduce_max_sync(0xffffffffu, la), 0);
            }
            // pack hots (each < 85) for cheap per-lane extraction
            unsigned plo = (unsigned)hot[0] | ((unsigned)hot[1] << 8) |
                           ((unsigned)hot[2] << 16) | ((unsigned)hot[3] << 24);
            unsigned phi = (unsigned)hot[4] | ((unsigned)hot[5] << 8) |
                           ((unsigned)hot[6] << 16) | ((unsigned)hot[7] << 24);

            // ---- per-anchor bookkeeping: lane j (0..7) owns anchor j ----
            if (lane < 8) {
                int h = (int)(((lane < 4 ? plo : phi) >> ((lane & 3) * 8)) & 0xffu);
                if (h > 0) {                          // positive (~2%): gather
                    float conf = -yp[base + lane * SLOTS + h];
                    accN++; accPos += conf;
                } else {                              // negative: bg preloaded
                    float conf = -bg;
                    int bin = (int)((conf - HIST_LO) * HIST_INVW);
                    bin = max(0, min(NBINS - 1, bin));
                    atomicAdd(&s_cnt[bin], 1);
                    atomicAdd(&s_sum[bin], conf);
                }
            }

            // ---- box smooth-L1: all 32 lanes, anchor j=lane>>2, coord=lane&3
            {
                int j = lane >> 2;
                int h = (int)(((j < 4 ? plo : phi) >> ((j & 3) * 8)) & 0xffu);
                if (h > 0) {                          // positives only (~2%)
                    unsigned rb = base + j * SLOTS + 81 + (lane & 3);
                    float d  = yp[rb] - yt[rb];
                    float ad = fabsf(d);
                    accLoc += (ad < 1.0f) ? 0.5f * d * d : (ad - 0.5f);
                }
            }
        } else {
            // ---- tail: per-anchor fallback (at most one warp) ----
            for (int j = 0; j < 8; j++) {
                if (a0 + j >= nanch) break;
                unsigned r = base + j * SLOTS;
                float t0 = yt[r + lane];
                float t1 = yt[r + lane + 32];
                float t2 = (lane < 17) ? yt[r + lane + 64] : 0.0f;
                int la = -1;
                if (t0 != 0.0f) la = lane;
                if (t1 != 0.0f) la = lane + 32;
                if (t2 != 0.0f) la = lane + 64;
                int hot = max(__reduce_max_sync(0xffffffffu, la), 0);
                if (lane == 0) {
                    float conf = -yp[r + hot];
                    if (hot > 0) { accN++; accPos += conf; }
                    else {
                        int bin = (int)((conf - HIST_LO) * HIST_INVW);
                        bin = max(0, min(NBINS - 1, bin));
                        atomicAdd(&s_cnt[bin], 1);
                        atomicAdd(&s_sum[bin], conf);
                    }
                }
                if (hot > 0 && lane >= 17 && lane < 21) {
                    unsigned rb = r + lane + 64;
                    float d  = yp[rb] - yt[rb];
                    float ad = fabsf(d);
                    accLoc += (ad < 1.0f) ? 0.5f * d * d : (ad - 0.5f);
                }
            }
        }
    }

    // ---- warp flush: reduce scattered accumulators, one atomic set per warp
    #pragma unroll
    for (int off = 16; off; off >>= 1) {
        accPos += __shfl_down_sync(0xffffffffu, accPos, off);
        accLoc += __shfl_down_sync(0xffffffffu, accLoc, off);
    }
    int warpN = __reduce_add_sync(0xffffffffu, accN);

    if (lane == 0) {
        if (warpN) {
            atomicAdd(&g_npos, warpN);
            atomicAdd(&g_pos_loss, (double)accPos);
        }
        if (accLoc != 0.0f) atomicAdd(&g_loc_loss, (double)accLoc);
    }

    __syncthreads();
    for (int i = threadIdx.x; i < NBINS; i += 256) {
        int cc = s_cnt[i];
        if (cc) {
            atomicAdd(&g_hist_cnt[i], cc);
            atomicAdd(&g_hist_sum[i], s_sum[i]);
        }
    }
}

// ---------------- K2: single-block finalize (warp-shuffle scan) ------------
__global__ __launch_bounds__(1024) void ssd_finalize_kernel(float* __restrict__ out)
{
    __shared__ int    s_wsum[32];
    __shared__ int    s_woff[32];
    __shared__ double s_neg;

    const int tid  = threadIdx.x;
    const int lane = tid & 31;
    const int wrp  = tid >> 5;

    // thread owns 4 consecutive ranks from the top: rank i -> bin NBINS-1-i
    int  c[4];
    float sf[4];
    #pragma unroll
    for (int k = 0; k < 4; k++) {
        int i = tid * 4 + k;
        int b = NBINS - 1 - i;
        c[k]  = g_hist_cnt[b];
        sf[k] = g_hist_sum[b];
    }
    int total = c[0] + c[1] + c[2] + c[3];

    // warp-local inclusive scan of per-thread totals
    int scan = total;
    #pragma unroll
    for (int off = 1; off < 32; off <<= 1) {
        int v = __shfl_up_sync(0xffffffffu, scan, off);
        if (lane >= off) scan += v;
    }
    if (lane == 31) s_wsum[wrp] = scan;
    if (tid == 0)   s_neg = 0.0;
    __syncthreads();

    // warp 0 scans the 32 warp totals -> exclusive warp offsets
    if (wrp == 0) {
        int w = s_wsum[lane];
        int ws = w;
        #pragma unroll
        for (int off = 1; off < 32; off <<= 1) {
            int v = __shfl_up_sync(0xffffffffu, ws, off);
            if (lane >= off) ws += v;
        }
        s_woff[lane] = ws - w;     // exclusive prefix
    }
    __syncthreads();

    int cumBefore = s_woff[wrp] + (scan - total);  // negatives strictly above

    int npos = g_npos;
    int nneg = (int)(3.0f * (float)npos);

    double contrib = 0.0;
    int cb = cumBefore;
    #pragma unroll
    for (int k = 0; k < 4; k++) {
        int cc = c[k];
        if (cc) {
            if (cb + cc <= nneg) {
                contrib += (double)sf[k];                                    // fully taken
            } else if (cb < nneg) {
                contrib += (double)sf[k] * (double)(nneg - cb) / (double)cc; // straddling
            }
        }
        cb += cc;
    }

    // warp-reduce contrib, one shared atomic per warp
    #pragma unroll
    for (int off = 16; off; off >>= 1)
        contrib += __shfl_down_sync(0xffffffffu, contrib, off);
    if (lane == 0 && contrib != 0.0) atomicAdd(&s_neg, contrib);
    __syncthreads();

    if (tid == 0) {
        double np = (npos > 0) ? (double)npos : 1.0;
        out[0] = (float)((g_pos_loss + s_neg + g_loc_loss) / np);
    }

    // ---- re-zero scratch so the next graph replay starts clean ----
    __syncthreads();
    for (int i = tid; i < NBINS; i += 1024) {
        g_hist_cnt[i] = 0;
        g_hist_sum[i] = 0.0f;
    }
    if (tid == 0) { g_npos = 0; g_pos_loss = 0.0; g_loc_loss = 0.0; }
}

// ---------------- entry point ----------------
extern "C" void kernel_launch(void* const* d_in, const int* in_sizes, int n_in,
                              void* d_out, int out_size)
{
    const float* y_pred = (const float*)d_in[0];
    const float* y_true = (const float*)d_in[1];
    float* out = (float*)d_out;

    int nanch = in_sizes[0] / SLOTS;

    ssd_main_kernel<<<NBLOCKS, 256>>>(y_pred, y_true, nanch);
    ssd_finalize_kernel<<<1, 1024>>>(out);
}

// round 10
// speedup vs baseline: 1.7181x; 1.0055x over previous
#include <cuda_runtime.h>
#include <math.h>

// ---------------- problem constants ----------------
#define SLOTS      85      // 81 classes + 4 box coords
#define NBINS      2048
#define HIST_LO   (-8.0f)
#define HIST_INVW (128.0f)   // NBINS / 16
#define NBLOCKS    592       // 4 blocks/SM (pinned) * 148 SMs = ONE wave

// ---------------- device scratch (statically zero-initialized; the fused
// finalize tail re-zeroes everything at the end of every replay) -----------
__device__ int      g_npos;
__device__ double   g_pos_loss;
__device__ double   g_loc_loss;
__device__ int      g_hist_cnt[NBINS];
__device__ float    g_hist_sum[NBINS];
__device__ unsigned g_done;

// ---------------- K1: one-hot gather pass, warp = 8 anchors ----------------
// y_true class rows are one-hot: conf = -y_pred[hot]. 25 independent LDGs are
// front-batched per iteration. The LAST block to finish runs the histogram
// top-k scan inline (saves a separate kernel launch).
__global__ __launch_bounds__(256, 4) void ssd_main_kernel(
    const float* __restrict__ yp,
    const float* __restrict__ yt,
    int nanch,
    float* __restrict__ out)
{
    __shared__ int   s_cnt[NBINS];
    __shared__ float s_sum[NBINS];
    __shared__ int   s_wsum[8];
    __shared__ int   s_woff[8];
    __shared__ double s_neg;
    __shared__ int   s_last;

    for (int i = threadIdx.x; i < NBINS; i += 256) { s_cnt[i] = 0; s_sum[i] = 0.0f; }
    __syncthreads();

    const int lane = threadIdx.x & 31;
    const int warp = threadIdx.x >> 5;

    const int wid    = blockIdx.x * 8 + warp;
    const int stride = NBLOCKS * 8 * 8;          // anchors per grid step

    float accPos = 0.0f, accLoc = 0.0f;
    int   accN = 0;

    for (int a0 = wid * 8; a0 < nanch; a0 += stride) {
        const unsigned base = (unsigned)a0 * SLOTS;   // fits: nanch*85 < 2^31

        if (a0 + 8 <= nanch) {
            // ---- 24 front-batched yt loads (immediates off one base) ----
            float ta[8], tb[8], tc[8];
            #pragma unroll
            for (int j = 0; j < 8; j++) {
                ta[j] = yt[base + j * SLOTS + lane];
                tb[j] = yt[base + j * SLOTS + lane + 32];
                tc[j] = (lane < 17) ? yt[base + j * SLOTS + lane + 64] : 0.0f;
            }
            // background logits: lane j<8 loads yp[(a0+j)*SLOTS]
            float bg = (lane < 8) ? yp[base + lane * SLOTS] : 0.0f;

            // ---- hot class index per anchor (one class slot nonzero) ----
            int hot[8];
            #pragma unroll
            for (int j = 0; j < 8; j++) {
                int la = -1;
                if (ta[j] != 0.0f) la = lane;
                if (tb[j] != 0.0f) la = lane + 32;
                if (tc[j] != 0.0f) la = lane + 64;   // tc==0 for lane>=17
                hot[j] = max(__reduce_max_sync(0xffffffffu, la), 0);
            }
            // pack hots (each < 85) for cheap per-lane extraction
            unsigned plo = (unsigned)hot[0] | ((unsigned)hot[1] << 8) |
                           ((unsigned)hot[2] << 16) | ((unsigned)hot[3] << 24);
            unsigned phi = (unsigned)hot[4] | ((unsigned)hot[5] << 8) |
                           ((unsigned)hot[6] << 16) | ((unsigned)hot[7] << 24);

            // ---- per-anchor bookkeeping: lane j (0..7) owns anchor j ----
            if (lane < 8) {
                int h = (int)(((lane < 4 ? plo : phi) >> ((lane & 3) * 8)) & 0xffu);
                if (h > 0) {                          // positive (~2%): gather
                    float conf = -yp[base + lane * SLOTS + h];
                    accN++; accPos += conf;
                } else {                              // negative: bg preloaded
                    float conf = -bg;
                    int bin = (int)((conf - HIST_LO) * HIST_INVW);
                    bin = max(0, min(NBINS - 1, bin));
                    atomicAdd(&s_cnt[bin], 1);
                    atomicAdd(&s_sum[bin], conf);
                }
            }

            // ---- box smooth-L1: all 32 lanes, anchor j=lane>>2, coord=lane&3
            {
                int j = lane >> 2;
                int h = (int)(((j < 4 ? plo : phi) >> ((j & 3) * 8)) & 0xffu);
                if (h > 0) {                          // positives only (~2%)
                    unsigned rb = base + j * SLOTS + 81 + (lane & 3);
                    float d  = yp[rb] - yt[rb];
                    float ad = fabsf(d);
                    accLoc += (ad < 1.0f) ? 0.5f * d * d : (ad - 0.5f);
                }
            }
        } else {
            // ---- tail: per-anchor fallback (at most one warp) ----
            for (int j = 0; j < 8; j++) {
                if (a0 + j >= nanch) break;
                unsigned r = base + j * SLOTS;
                float t0 = yt[r + lane];
                float t1 = yt[r + lane + 32];
                float t2 = (lane < 17) ? yt[r + lane + 64] : 0.0f;
                int la = -1;
                if (t0 != 0.0f) la = lane;
                if (t1 != 0.0f) la = lane + 32;
                if (t2 != 0.0f) la = lane + 64;
                int hot = max(__reduce_max_sync(0xffffffffu, la), 0);
                if (lane == 0) {
                    float conf = -yp[r + hot];
                    if (hot > 0) { accN++; accPos += conf; }
                    else {
                        int bin = (int)((conf - HIST_LO) * HIST_INVW);
                        bin = max(0, min(NBINS - 1, bin));
                        atomicAdd(&s_cnt[bin], 1);
                        atomicAdd(&s_sum[bin], conf);
                    }
                }
                if (hot > 0 && lane >= 17 && lane < 21) {
                    unsigned rb = r + lane + 64;
                    float d  = yp[rb] - yt[rb];
                    float ad = fabsf(d);
                    accLoc += (ad < 1.0f) ? 0.5f * d * d : (ad - 0.5f);
                }
            }
        }
    }

    // ---- warp flush: reduce scattered accumulators, one atomic set per warp
    #pragma unroll
    for (int off = 16; off; off >>= 1) {
        accPos += __shfl_down_sync(0xffffffffu, accPos, off);
        accLoc += __shfl_down_sync(0xffffffffu, accLoc, off);
    }
    int warpN = __reduce_add_sync(0xffffffffu, accN);

    if (lane == 0) {
        if (warpN) {
            atomicAdd(&g_npos, warpN);
            atomicAdd(&g_pos_loss, (double)accPos);
        }
        if (accLoc != 0.0f) atomicAdd(&g_loc_loss, (double)accLoc);
    }

    __syncthreads();
    for (int i = threadIdx.x; i < NBINS; i += 256) {
        int cc = s_cnt[i];
        if (cc) {
            atomicAdd(&g_hist_cnt[i], cc);
            atomicAdd(&g_hist_sum[i], s_sum[i]);
        }
    }

    // ================= fused finalize: last block does the top-k scan =======
    __threadfence();                       // make this block's writes visible
    __syncthreads();
    if (threadIdx.x == 0) {
        unsigned old = atomicAdd(&g_done, 1u);
        s_last = (old == (unsigned)(gridDim.x - 1)) ? 1 : 0;
    }
    __syncthreads();
    if (!s_last) return;

    __threadfence();                       // acquire all blocks' writes

    const int tid = threadIdx.x;
    const int wrp = tid >> 5;

    // thread owns 8 consecutive ranks from the top: rank i -> bin NBINS-1-i
    int   c[8];
    float sf[8];
    #pragma unroll
    for (int k = 0; k < 8; k++) {
        int b = NBINS - 1 - (tid * 8 + k);
        c[k]  = g_hist_cnt[b];
        sf[k] = g_hist_sum[b];
    }
    int total = 0;
    #pragma unroll
    for (int k = 0; k < 8; k++) total += c[k];

    // warp-local inclusive scan of per-thread totals
    int scan = total;
    #pragma unroll
    for (int off = 1; off < 32; off <<= 1) {
        int v = __shfl_up_sync(0xffffffffu, scan, off);
        if (lane >= off) scan += v;
    }
    if (lane == 31) s_wsum[wrp] = scan;
    if (tid == 0)   s_neg = 0.0;
    __syncthreads();

    // warp 0 scans the 8 warp totals -> exclusive warp offsets
    if (wrp == 0) {
        int w = (lane < 8) ? s_wsum[lane] : 0;
        int ws = w;
        #pragma unroll
        for (int off = 1; off < 8; off <<= 1) {
            int v = __shfl_up_sync(0xffffffffu, ws, off);
            if (lane >= off) ws += v;
        }
        if (lane < 8) s_woff[lane] = ws - w;   // exclusive prefix
    }
    __syncthreads();

    int cumBefore = s_woff[wrp] + (scan - total);  // negatives strictly above

    int npos = g_npos;
    int nneg = (int)(3.0f * (float)npos);

    double contrib = 0.0;
    int cb = cumBefore;
    #pragma unroll
    for (int k = 0; k < 8; k++) {
        int cc = c[k];
        if (cc) {
            if (cb + cc <= nneg) {
                contrib += (double)sf[k];                                    // fully taken
            } else if (cb < nneg) {
                contrib += (double)sf[k] * (double)(nneg - cb) / (double)cc; // straddling
            }
        }
        cb += cc;
    }

    // warp-reduce contrib, one shared atomic per warp
    #pragma unroll
    for (int off = 16; off; off >>= 1)
        contrib += __shfl_down_sync(0xffffffffu, contrib, off);
    if (lane == 0 && contrib != 0.0) atomicAdd(&s_neg, contrib);
    __syncthreads();

    if (tid == 0) {
        double np = (npos > 0) ? (double)npos : 1.0;
        out[0] = (float)((g_pos_loss + s_neg + g_loc_loss) / np);
    }

    // ---- re-zero scratch so the next graph replay starts clean ----
    __syncthreads();
    for (int i = tid; i < NBINS; i += 256) {
        g_hist_cnt[i] = 0;
        g_hist_sum[i] = 0.0f;
    }
    if (tid == 0) {
        g_npos = 0; g_pos_loss = 0.0; g_loc_loss = 0.0; g_done = 0u;
    }
}

// ---------------- entry point ----------------
extern "C" void kernel_launch(void* const* d_in, const int* in_sizes, int n_in,
                              void* d_out, int out_size)
{
    const float* y_pred = (const float*)d_in[0];
    const float* y_true = (const float*)d_in[1];
    float* out = (float*)d_out;

    int nanch = in_sizes[0] / SLOTS;

    ssd_main_kernel<<<NBLOCKS, 256>>>(y_pred, y_true, nanch, out);
}

// round 11
// speedup vs baseline: 1.7408x; 1.0132x over previous
#include <cuda_runtime.h>
#include <math.h>

// ---------------- problem constants ----------------
#define SLOTS      85      // 81 classes + 4 box coords
#define NBINS      2048
#define HIST_LO   (-8.0f)
#define HIST_INVW (128.0f)   // NBINS / 16
#define NBLOCKS    592       // 4 blocks/SM (pinned) * 148 SMs = ONE wave

// ---------------- device scratch (statically zero-initialized; the fused
// finalize tail re-zeroes everything at the end of every replay) -----------
__device__ int      g_npos;
__device__ double   g_pos_loss;
__device__ double   g_loc_loss;
__device__ int      g_hist_cnt[NBINS];
__device__ float    g_hist_sum[NBINS];
__device__ unsigned g_done;

// ---------------- K1: one-hot gather pass, warp = 8 anchors ----------------
// y_true class rows are one-hot: conf = -y_pred[hot]. 25 independent LDGs are
// front-batched per iteration. Hot slots are OR-packed per anchor (8 bits
// each) and reduced with TWO __reduce_or_sync ops (one-hot => OR-safe),
// replacing eight __reduce_max_sync. The LAST block to finish runs the
// histogram top-k scan inline.
__global__ __launch_bounds__(256, 4) void ssd_main_kernel(
    const float* __restrict__ yp,
    const float* __restrict__ yt,
    int nanch,
    float* __restrict__ out)
{
    __shared__ int   s_cnt[NBINS];
    __shared__ float s_sum[NBINS];
    __shared__ int   s_wsum[8];
    __shared__ int   s_woff[8];
    __shared__ double s_neg;
    __shared__ int   s_last;

    for (int i = threadIdx.x; i < NBINS; i += 256) { s_cnt[i] = 0; s_sum[i] = 0.0f; }
    __syncthreads();

    const int lane = threadIdx.x & 31;
    const int warp = threadIdx.x >> 5;

    const int wid    = blockIdx.x * 8 + warp;
    const int stride = NBLOCKS * 8 * 8;          // anchors per grid step

    float accPos = 0.0f, accLoc = 0.0f;
    int   accN = 0;

    for (int a0 = wid * 8; a0 < nanch; a0 += stride) {
        const unsigned base = (unsigned)a0 * SLOTS;   // fits: nanch*85 < 2^31

        if (a0 + 8 <= nanch) {
            // ---- 24 front-batched yt loads (immediates off one base) ----
            float ta[8], tb[8], tc[8];
            #pragma unroll
            for (int j = 0; j < 8; j++) {
                ta[j] = yt[base + j * SLOTS + lane];
                tb[j] = yt[base + j * SLOTS + lane + 32];
                tc[j] = (lane < 17) ? yt[base + j * SLOTS + lane + 64] : 0.0f;
            }
            // background logits: lane j<8 loads yp[(a0+j)*SLOTS]
            float bg = (lane < 8) ? yp[base + lane * SLOTS] : 0.0f;

            // ---- hot slots: OR-pack 4 anchors per word, 2 redux total ----
            // one-hot rows => at most one lane contributes per anchor, and
            // slot 0 (background) ORs as 0, which is exactly hot==0.
            unsigned plo = 0u, phi = 0u;
            #pragma unroll
            for (int j = 0; j < 4; j++) {
                unsigned slot = 0u;
                if (ta[j] != 0.0f) slot = (unsigned)lane;
                if (tb[j] != 0.0f) slot = (unsigned)(lane + 32);
                if (tc[j] != 0.0f) slot = (unsigned)(lane + 64);  // lane<17 only
                plo |= slot << (j * 8);
            }
            #pragma unroll
            for (int j = 4; j < 8; j++) {
                unsigned slot = 0u;
                if (ta[j] != 0.0f) slot = (unsigned)lane;
                if (tb[j] != 0.0f) slot = (unsigned)(lane + 32);
                if (tc[j] != 0.0f) slot = (unsigned)(lane + 64);
                phi |= slot << ((j - 4) * 8);
            }
            plo = __reduce_or_sync(0xffffffffu, plo);
            phi = __reduce_or_sync(0xffffffffu, phi);

            // ---- per-anchor bookkeeping: lane j (0..7) owns anchor j ----
            if (lane < 8) {
                int h = (int)(((lane < 4 ? plo : phi) >> ((lane & 3) * 8)) & 0xffu);
                if (h > 0) {                          // positive (~2%): gather
                    float conf = -yp[base + lane * SLOTS + h];
                    accN++; accPos += conf;
                } else {                              // negative: bg preloaded
                    float conf = -bg;
                    int bin = (int)((conf - HIST_LO) * HIST_INVW);
                    bin = max(0, min(NBINS - 1, bin));
                    atomicAdd(&s_cnt[bin], 1);
                    atomicAdd(&s_sum[bin], conf);
                }
            }

            // ---- box smooth-L1: all 32 lanes, anchor j=lane>>2, coord=lane&3
            {
                int j = lane >> 2;
                int h = (int)(((j < 4 ? plo : phi) >> ((j & 3) * 8)) & 0xffu);
                if (h > 0) {                          // positives only (~2%)
                    unsigned rb = base + j * SLOTS + 81 + (lane & 3);
                    float d  = yp[rb] - yt[rb];
                    float ad = fabsf(d);
                    accLoc += (ad < 1.0f) ? 0.5f * d * d : (ad - 0.5f);
                }
            }
        } else {
            // ---- tail: per-anchor fallback (at most one warp) ----
            for (int j = 0; j < 8; j++) {
                if (a0 + j >= nanch) break;
                unsigned r = base + j * SLOTS;
                float t0 = yt[r + lane];
                float t1 = yt[r + lane + 32];
                float t2 = (lane < 17) ? yt[r + lane + 64] : 0.0f;
                int la = -1;
                if (t0 != 0.0f) la = lane;
                if (t1 != 0.0f) la = lane + 32;
                if (t2 != 0.0f) la = lane + 64;
                int hot = max(__reduce_max_sync(0xffffffffu, la), 0);
                if (lane == 0) {
                    float conf = -yp[r + hot];
                    if (hot > 0) { accN++; accPos += conf; }
                    else {
                        int bin = (int)((conf - HIST_LO) * HIST_INVW);
                        bin = max(0, min(NBINS - 1, bin));
                        atomicAdd(&s_cnt[bin], 1);
                        atomicAdd(&s_sum[bin], conf);
                    }
                }
                if (hot > 0 && lane >= 17 && lane < 21) {
                    unsigned rb = r + lane + 64;
                    float d  = yp[rb] - yt[rb];
                    float ad = fabsf(d);
                    accLoc += (ad < 1.0f) ? 0.5f * d * d : (ad - 0.5f);
                }
            }
        }
    }

    // ---- warp flush: reduce scattered accumulators, one atomic set per warp
    #pragma unroll
    for (int off = 16; off; off >>= 1) {
        accPos += __shfl_down_sync(0xffffffffu, accPos, off);
        accLoc += __shfl_down_sync(0xffffffffu, accLoc, off);
    }
    int warpN = __reduce_add_sync(0xffffffffu, accN);

    if (lane == 0) {
        if (warpN) {
            atomicAdd(&g_npos, warpN);
            atomicAdd(&g_pos_loss, (double)accPos);
        }
        if (accLoc != 0.0f) atomicAdd(&g_loc_loss, (double)accLoc);
    }

    __syncthreads();
    for (int i = threadIdx.x; i < NBINS; i += 256) {
        int cc = s_cnt[i];
        if (cc) {
            atomicAdd(&g_hist_cnt[i], cc);
            atomicAdd(&g_hist_sum[i], s_sum[i]);
        }
    }

    // ================= fused finalize: last block does the top-k scan =======
    __threadfence();                       // make this block's writes visible
    __syncthreads();
    if (threadIdx.x == 0) {
        unsigned old = atomicAdd(&g_done, 1u);
        s_last = (old == (unsigned)(gridDim.x - 1)) ? 1 : 0;
    }
    __syncthreads();
    if (!s_last) return;

    __threadfence();                       // acquire all blocks' writes

    const int tid = threadIdx.x;
    const int wrp = tid >> 5;

    // thread owns 8 consecutive ranks from the top: rank i -> bin NBINS-1-i
    int   c[8];
    float sf[8];
    #pragma unroll
    for (int k = 0; k < 8; k++) {
        int b = NBINS - 1 - (tid * 8 + k);
        c[k]  = g_hist_cnt[b];
        sf[k] = g_hist_sum[b];
    }
    int total = 0;
    #pragma unroll
    for (int k = 0; k < 8; k++) total += c[k];

    // warp-local inclusive scan of per-thread totals
    int scan = total;
    #pragma unroll
    for (int off = 1; off < 32; off <<= 1) {
        int v = __shfl_up_sync(0xffffffffu, scan, off);
        if (lane >= off) scan += v;
    }
    if (lane == 31) s_wsum[wrp] = scan;
    if (tid == 0)   s_neg = 0.0;
    __syncthreads();

    // warp 0 scans the 8 warp totals -> exclusive warp offsets
    if (wrp == 0) {
        int w = (lane < 8) ? s_wsum[lane] : 0;
        int ws = w;
        #pragma unroll
        for (int off = 1; off < 8; off <<= 1) {
            int v = __shfl_up_sync(0xffffffffu, ws, off);
            if (lane >= off) ws += v;
        }
        if (lane < 8) s_woff[lane] = ws - w;   // exclusive prefix
    }
    __syncthreads();

    int cumBefore = s_woff[wrp] + (scan - total);  // negatives strictly above

    int npos = g_npos;
    int nneg = (int)(3.0f * (float)npos);

    double contrib = 0.0;
    int cb = cumBefore;
    #pragma unroll
    for (int k = 0; k < 8; k++) {
        int cc = c[k];
        if (cc) {
            if (cb + cc <= nneg) {
                contrib += (double)sf[k];                                    // fully taken
            } else if (cb < nneg) {
                contrib += (double)sf[k] * (double)(nneg - cb) / (double)cc; // straddling
            }
        }
        cb += cc;
    }

    // warp-reduce contrib, one shared atomic per warp
    #pragma unroll
    for (int off = 16; off; off >>= 1)
        contrib += __shfl_down_sync(0xffffffffu, contrib, off);
    if (lane == 0 && contrib != 0.0) atomicAdd(&s_neg, contrib);
    __syncthreads();

    if (tid == 0) {
        double np = (npos > 0) ? (double)npos : 1.0;
        out[0] = (float)((g_pos_loss + s_neg + g_loc_loss) / np);
    }

    // ---- re-zero scratch so the next graph replay starts clean ----
    __syncthreads();
    for (int i = tid; i < NBINS; i += 256) {
        g_hist_cnt[i] = 0;
        g_hist_sum[i] = 0.0f;
    }
    if (tid == 0) {
        g_npos = 0; g_pos_loss = 0.0; g_loc_loss = 0.0; g_done = 0u;
    }
}

// ---------------- entry point ----------------
extern "C" void kernel_launch(void* const* d_in, const int* in_sizes, int n_in,
                              void* d_out, int out_size)
{
    const float* y_pred = (const float*)d_in[0];
    const float* y_true = (const float*)d_in[1];
    float* out = (float*)d_out;

    int nanch = in_sizes[0] / SLOTS;

    ssd_main_kernel<<<NBLOCKS, 256>>>(y_pred, y_true, nanch, out);
}